// round 4
// baseline (speedup 1.0000x reference)
#include <cuda_runtime.h>
#include <cuda_bf16.h>
#include <cstdint>
#include <cstddef>

#define NBX  1024      // boxes
#define NCLS 151       // classes incl background
#define NNMS 150       // nms classes
#define RELK 4096
#define RELM 4096
#define RELN 51
#define RELNP 64       // padded cols
#define GK   32        // gemm k-chunk

// ---------------- persistent device scratch (no allocation allowed) --------
static __device__ float                g_probs[NBX * NCLS];
static __device__ int                  g_order[NNMS * NBX];
static __device__ __align__(16) float4 g_sbox[NNMS * NBX];
static __device__ float                g_sarea[NNMS * NBX];
// mask layout: [class][colgroup(16)][row i (1024)]  (coalesced writes)
static __device__ unsigned long long   g_mask[(size_t)NNMS * 16 * NBX];
static __device__ unsigned char        g_keep[NNMS * NBX];
static __device__ __align__(16) float  g_Wt[RELK * RELNP];   // W^T zero-padded (cols 51..63 stay 0)
static __device__ float                g_psum[4 * (size_t)RELM * RELNP];

// ---------------- f32x2 packed-math helpers --------------------------------
__device__ __forceinline__ unsigned long long dup2(float x) {
    unsigned long long r;
    asm("mov.b64 %0, {%1, %1};" : "=l"(r) : "f"(x));
    return r;
}
__device__ __forceinline__ void ffma2(unsigned long long& d,
                                      unsigned long long a,
                                      unsigned long long b) {
    asm("fma.rn.f32x2 %0, %1, %2, %0;" : "+l"(d) : "l"(a), "l"(b));
}
__device__ __forceinline__ void unpack2(unsigned long long v, float& lo, float& hi) {
    unsigned a, b;
    asm("mov.b64 {%0, %1}, %2;" : "=r"(a), "=r"(b) : "l"(v));
    lo = __uint_as_float(a);
    hi = __uint_as_float(b);
}

// ---------------- 1) softmax per box + copy logits to out ------------------
// one warp per box; 151 classes -> 5 strided elements per lane
__global__ void softmax_kernel(const float* __restrict__ logits, float* __restrict__ out) {
    int warp = (blockIdx.x * blockDim.x + threadIdx.x) >> 5;
    int lane = threadIdx.x & 31;
    if (warp >= NBX) return;
    const float* row = logits + (size_t)warp * NCLS;

    float v[5];
    float mx = -3.402823466e38f;
#pragma unroll
    for (int j = 0; j < 5; j++) {
        int c = lane + j * 32;
        v[j]  = (c < NCLS) ? row[c] : -3.402823466e38f;
        mx    = fmaxf(mx, v[j]);
    }
#pragma unroll
    for (int o = 16; o; o >>= 1) mx = fmaxf(mx, __shfl_xor_sync(0xffffffffu, mx, o));

    float s = 0.f;
#pragma unroll
    for (int j = 0; j < 5; j++) {
        int c = lane + j * 32;
        if (c < NCLS) {
            v[j] = expf(__fsub_rn(v[j], mx));
            s    = __fadd_rn(s, v[j]);
        }
    }
#pragma unroll
    for (int o = 16; o; o >>= 1) s = __fadd_rn(s, __shfl_xor_sync(0xffffffffu, s, o));

#pragma unroll
    for (int j = 0; j < 5; j++) {
        int c = lane + j * 32;
        if (c < NCLS) {
            g_probs[(size_t)warp * NCLS + c] = __fdiv_rn(v[j], s);
            out[(size_t)warp * NCLS + c]     = row[c];   // obj_dists2 = logits verbatim
        }
    }
}

// ---------------- 2) W transpose + zero-pad --------------------------------
__global__ void wprep_kernel(const float* __restrict__ W) {
    int idx = blockIdx.x * 256 + threadIdx.x;    // over 51*4096, coalesced reads
    if (idx >= RELN * RELK) return;
    int c = idx >> 12;          // 0..50
    int k = idx & 4095;
    g_Wt[(size_t)k * RELNP + c] = W[idx];
}

// ---------------- 3) per-class stable descending sort (bitonic, 1024) ------
// key = (score_bits << 32) | (1023 - idx): descending score, ascending idx on ties
__global__ void sort_kernel(const float* __restrict__ boxes) {
    __shared__ unsigned long long key[NBX];
    int c = blockIdx.x;          // nms class 0..149 -> real class c+1
    int t = threadIdx.x;         // 0..511

#pragma unroll
    for (int e = 0; e < 2; e++) {
        int i = t + e * 512;
        unsigned sb = __float_as_uint(g_probs[(size_t)i * NCLS + c + 1]);  // probs >= 0
        key[i] = ((unsigned long long)sb << 32) | (unsigned)(1023 - i);
    }
    __syncthreads();

    for (int k = 2; k <= 1024; k <<= 1) {
        for (int j = k >> 1; j > 0; j >>= 1) {
#pragma unroll
            for (int e = 0; e < 2; e++) {
                int tid = t + e * 512;
                int ixj = tid ^ j;
                if (ixj > tid) {
                    bool desc = ((tid & k) == 0);   // descending overall
                    unsigned long long a = key[tid], b = key[ixj];
                    bool sw = desc ? (a < b) : (a > b);
                    if (sw) { key[tid] = b; key[ixj] = a; }
                }
            }
            __syncthreads();
        }
    }

#pragma unroll
    for (int e = 0; e < 2; e++) {
        int i   = t + e * 512;
        int idx = 1023 - (int)(key[i] & 1023u);
        g_order[c * NBX + i] = idx;
        const float4 bx = *reinterpret_cast<const float4*>(
            boxes + ((size_t)idx * NCLS + c + 1) * 4);
        g_sbox[c * NBX + i]  = bx;
        // ref: area = (x2-x1)*(y2-y1), exact rounding order
        g_sarea[c * NBX + i] = __fmul_rn(__fsub_rn(bx.z, bx.x), __fsub_rn(bx.w, bx.y));
    }
}

// ---------------- 4) pairwise suppression mask (triangular blocks) ---------
// grid (cb=16, rb=16, class=150), 64 threads; thread = row box, loops 64 col boxes
__global__ void mask_kernel() {
    int cb = blockIdx.x, rb = blockIdx.y, c = blockIdx.z;
    int t  = threadIdx.x;                       // 0..63
    int i  = rb * 64 + t;                       // sorted row index
    unsigned long long* mp = g_mask + ((size_t)c * 16 + cb) * NBX + i;

    if (cb < rb) { *mp = 0ULL; return; }        // only j>i matters; zero lower blocks

    __shared__ float4 cbox[64];
    __shared__ float  carea[64];
    cbox[t]  = g_sbox[c * NBX + cb * 64 + t];
    carea[t] = g_sarea[c * NBX + cb * 64 + t];
    __syncthreads();

    float4 rbx = g_sbox[c * NBX + i];
    float  ra  = g_sarea[c * NBX + i];

    unsigned long long bits = 0ULL;
#pragma unroll 4
    for (int j = 0; j < 64; j++) {
        float4 cj = cbox[j];
        float ix1 = fmaxf(rbx.x, cj.x);
        float iy1 = fmaxf(rbx.y, cj.y);
        float ix2 = fminf(rbx.z, cj.z);
        float iy2 = fminf(rbx.w, cj.w);
        float iw  = fmaxf(__fsub_rn(ix2, ix1), 0.f);
        float ih  = fmaxf(__fsub_rn(iy2, iy1), 0.f);
        float inter = __fmul_rn(iw, ih);
        // ref order: ((area_i + area_j) - inter) + 1e-10
        float denom = __fadd_rn(__fsub_rn(__fadd_rn(ra, carea[j]), inter), 1e-10f);
        // fast multiply-compare with ambiguity band; exact div fallback
        float hi = __fmul_rn(denom, 0.30005f);
        float lo = __fmul_rn(denom, 0.29995f);
        bool sup;
        if (inter >= hi)      sup = true;
        else if (inter <= lo) sup = false;
        else                  sup = (__fdiv_rn(inter, denom) > 0.3f);
        if (sup) bits |= (1ULL << j);
    }
    *mp = bits;   // coalesced (64 consecutive ULLs)
}

// ---------------- 5) greedy scan: two-level, register-resident -------------
// 1 block of 16 lanes per class. Lane l owns column-group l (64 bits).
// Per 64-row group g: every lane preloads its 64-row chunk into registers
// (independent LDGs -> one memory round-trip), lane g runs the serial keep
// chain ALU-only, one shfl broadcasts the keep word, all lanes OR kept rows.
__global__ void scan_kernel() {
    int c    = blockIdx.x;
    int lane = threadIdx.x;   // 0..15
    const unsigned long long* mcol = g_mask + ((size_t)c * 16 + lane) * NBX;
    const int* ord = g_order + c * NBX;
    unsigned char* kp = g_keep + c * NBX;

    unsigned long long remv = 0ULL;   // suppressed bits in this lane's column group
    for (int g = 0; g < 16; g++) {
        // stage this lane's 64-row chunk into registers (full unroll -> MLP)
        unsigned long long v[64];
        const unsigned long long* p = mcol + g * 64;
#pragma unroll
        for (int r = 0; r < 64; r++) v[r] = __ldg(p + r);

        // serial in-group chain, owner lane only, pure ALU
        unsigned long long kb = 0ULL;
        if (lane == g) {
            unsigned long long rg = remv;
#pragma unroll
            for (int r = 0; r < 64; r++) {
                if (((rg >> r) & 1ULL) == 0ULL) {
                    kb |= (1ULL << r);
                    rg |= v[r];       // over-OR of bits <= r is safe (already decided)
                }
            }
            remv = rg;
        }
        kb = __shfl_sync(0xffffu, kb, g);

        // all lanes accumulate suppressions from kept rows (uniform guard)
        unsigned long long acc = remv;
#pragma unroll
        for (int r = 0; r < 64; r++) {
            if ((kb >> r) & 1ULL) acc |= v[r];
        }
        remv = acc;

        if (lane == 0) {
#pragma unroll
            for (int r = 0; r < 64; r++)
                kp[ord[g * 64 + r]] = (unsigned char)((kb >> r) & 1ULL);
        }
    }
}

// ---------------- 6) argmax over masked probs -> obj_preds -----------------
__global__ void argmax_kernel(float* __restrict__ out) {
    int n = blockIdx.x * 256 + threadIdx.x;
    if (n >= NBX) return;
    float best = -1.f;
    int   bc   = 0;
    for (int c = 0; c < NNMS; c++) {
        float v = g_keep[c * NBX + n] ? g_probs[(size_t)n * NCLS + c + 1] : 0.f;
        if (v > best) { best = v; bc = c; }   // strict > == jnp.argmax first-max
    }
    out[154624 + n] = (float)(bc + 1);
}

// ---------------- 7) GEMM partial: vr @ Wt, split-K x4, f32x2 packed -------
// block tile: 128 rows x 64 cols, 256 threads; thread: 8 rows (4 row-pairs) x 4 cols
__global__ void __launch_bounds__(256) gemm_kernel(const float* __restrict__ A) {
    __shared__ __align__(16) float As[GK][132];   // [k][m], 528B row stride (16B-aligned)
    __shared__ __align__(16) float Bs[GK][64];    // [k][c]

    int tid = threadIdx.x;
    int rt  = blockIdx.x;       // 0..31 row tile
    int z   = blockIdx.y;       // 0..3  k-split
    int m0  = rt * 128;
    int k0  = z * 1024;
    int tc  = tid & 15;         // col group: cols tc*4..tc*4+3
    int tr  = tid >> 4;         // row group: rows tr*8..tr*8+7

    unsigned long long acc[4][4];
#pragma unroll
    for (int a = 0; a < 4; a++)
#pragma unroll
        for (int b = 0; b < 4; b++) acc[a][b] = 0ULL;

    const float* Ag = A + (size_t)m0 * RELK + k0;

    for (int kc = 0; kc < 1024; kc += GK) {
        // A tile 128x32 -> As[k][m] (transpose in smem)
#pragma unroll
        for (int it = 0; it < 4; it++) {
            int idx = tid + it * 256;       // 0..1023
            int m   = idx >> 3;             // 0..127
            int k4  = (idx & 7) * 4;
            float4 v = *reinterpret_cast<const float4*>(Ag + (size_t)m * RELK + kc + k4);
            As[k4 + 0][m] = v.x;
            As[k4 + 1][m] = v.y;
            As[k4 + 2][m] = v.z;
            As[k4 + 3][m] = v.w;
        }
        // B tile 32x64
#pragma unroll
        for (int it = 0; it < 2; it++) {
            int f  = tid + it * 256;        // float4 id over 512
            int k  = f >> 4;
            int c4 = (f & 15) * 4;
            *reinterpret_cast<float4*>(&Bs[k][c4]) =
                *reinterpret_cast<const float4*>(g_Wt + (size_t)(k0 + kc + k) * RELNP + c4);
        }
        __syncthreads();

#pragma unroll
        for (int k = 0; k < GK; k++) {
            longlong2 aA = *reinterpret_cast<const longlong2*>(&As[k][tr * 8]);
            longlong2 aB = *reinterpret_cast<const longlong2*>(&As[k][tr * 8 + 4]);
            unsigned long long ar[4] = { (unsigned long long)aA.x, (unsigned long long)aA.y,
                                         (unsigned long long)aB.x, (unsigned long long)aB.y };
            float4 bv = *reinterpret_cast<const float4*>(&Bs[k][tc * 4]);
            unsigned long long bd[4] = { dup2(bv.x), dup2(bv.y), dup2(bv.z), dup2(bv.w) };
#pragma unroll
            for (int rp = 0; rp < 4; rp++)
#pragma unroll
                for (int cc = 0; cc < 4; cc++) ffma2(acc[rp][cc], ar[rp], bd[cc]);
        }
        __syncthreads();
    }

    float* P = g_psum + ((size_t)z * RELM + m0) * RELNP;
#pragma unroll
    for (int rp = 0; rp < 4; rp++) {
        int mr = tr * 8 + rp * 2;
#pragma unroll
        for (int cc = 0; cc < 4; cc++) {
            float lo, hi;
            unpack2(acc[rp][cc], lo, hi);
            P[(size_t)(mr + 0) * RELNP + tc * 4 + cc] = lo;
            P[(size_t)(mr + 1) * RELNP + tc * 4 + cc] = hi;
        }
    }
}

// ---------------- 8) split-K reduce + bias -> rel_dists --------------------
__global__ void reduce_kernel(const float* __restrict__ b, float* __restrict__ out) {
    int idx = blockIdx.x * 256 + threadIdx.x;
    if (idx >= RELM * RELN) return;
    int m = idx / RELN;
    int c = idx - m * RELN;
    float s = b[c];
#pragma unroll
    for (int z = 0; z < 4; z++) s += g_psum[((size_t)z * RELM + m) * RELNP + c];
    out[154624 + 1024 + idx] = s;
}

// ---------------- launch ----------------------------------------------------
extern "C" void kernel_launch(void* const* d_in, const int* in_sizes, int n_in,
                              void* d_out, int out_size) {
    const float *logits = nullptr, *vr = nullptr, *boxes = nullptr, *W = nullptr, *bb = nullptr;
    for (int i = 0; i < n_in; i++) {
        switch (in_sizes[i]) {
            case 154624:   logits = (const float*)d_in[i]; break;  // obj_logits 1024x151
            case 16777216: vr     = (const float*)d_in[i]; break;  // vr 4096x4096
            case 618496:   boxes  = (const float*)d_in[i]; break;  // boxes_per_cls 1024x151x4
            case 208896:   W      = (const float*)d_in[i]; break;  // W 51x4096
            case 51:       bb     = (const float*)d_in[i]; break;  // b 51
        }
    }
    float* out = (float*)d_out;

    softmax_kernel<<<128, 256>>>(logits, out);
    wprep_kernel<<<(RELN * RELK + 255) / 256, 256>>>(W);
    sort_kernel<<<NNMS, 512>>>(boxes);
    mask_kernel<<<dim3(16, 16, NNMS), 64>>>();
    scan_kernel<<<NNMS, 16>>>();
    argmax_kernel<<<4, 256>>>(out);
    gemm_kernel<<<dim3(32, 4), 256>>>(vr);
    reduce_kernel<<<(RELM * RELN + 255) / 256, 256>>>(bb, out);
}

// round 5
// speedup vs baseline: 1.0756x; 1.0756x over previous
#include <cuda_runtime.h>
#include <cuda_bf16.h>
#include <cstdint>
#include <cstddef>

#define NBX  1024      // boxes
#define NCLS 151       // classes incl background
#define NNMS 150       // nms classes
#define RELK 4096
#define RELM 4096
#define RELN 51
#define RELNP 64       // padded cols
#define GK   32        // gemm k-chunk
#define KSPL 8         // split-K factor
#define KPER (RELK / KSPL)        // 512 k per split
#define NCH  (KPER / GK)          // 16 chunks per split

// ---------------- persistent device scratch (no allocation allowed) --------
static __device__ float                g_probs[NBX * NCLS];
static __device__ int                  g_order[NNMS * NBX];
static __device__ __align__(16) float4 g_sbox[NNMS * NBX];
static __device__ float                g_sarea[NNMS * NBX];
// mask layout: [class][colgroup64(16)][row i (1024)]  (coalesced writes)
static __device__ unsigned long long   g_mask[(size_t)NNMS * 16 * NBX];
static __device__ unsigned char        g_keep[NNMS * NBX];
static __device__ __align__(16) float  g_Wt[RELK * RELNP];   // W^T zero-padded (cols 51..63 stay 0)
static __device__ float                g_psum[KSPL * (size_t)RELM * RELNP];

// ---------------- f32x2 packed-math helpers --------------------------------
__device__ __forceinline__ unsigned long long dup2(float x) {
    unsigned long long r;
    asm("mov.b64 %0, {%1, %1};" : "=l"(r) : "f"(x));
    return r;
}
__device__ __forceinline__ void ffma2(unsigned long long& d,
                                      unsigned long long a,
                                      unsigned long long b) {
    asm("fma.rn.f32x2 %0, %1, %2, %0;" : "+l"(d) : "l"(a), "l"(b));
}
__device__ __forceinline__ void unpack2(unsigned long long v, float& lo, float& hi) {
    unsigned a, b;
    asm("mov.b64 {%0, %1}, %2;" : "=r"(a), "=r"(b) : "l"(v));
    lo = __uint_as_float(a);
    hi = __uint_as_float(b);
}

// ---------------- 1) softmax per box + copy logits to out ------------------
__global__ void softmax_kernel(const float* __restrict__ logits, float* __restrict__ out) {
    int warp = (blockIdx.x * blockDim.x + threadIdx.x) >> 5;
    int lane = threadIdx.x & 31;
    if (warp >= NBX) return;
    const float* row = logits + (size_t)warp * NCLS;

    float v[5];
    float mx = -3.402823466e38f;
#pragma unroll
    for (int j = 0; j < 5; j++) {
        int c = lane + j * 32;
        v[j]  = (c < NCLS) ? row[c] : -3.402823466e38f;
        mx    = fmaxf(mx, v[j]);
    }
#pragma unroll
    for (int o = 16; o; o >>= 1) mx = fmaxf(mx, __shfl_xor_sync(0xffffffffu, mx, o));

    float s = 0.f;
#pragma unroll
    for (int j = 0; j < 5; j++) {
        int c = lane + j * 32;
        if (c < NCLS) {
            v[j] = expf(__fsub_rn(v[j], mx));
            s    = __fadd_rn(s, v[j]);
        }
    }
#pragma unroll
    for (int o = 16; o; o >>= 1) s = __fadd_rn(s, __shfl_xor_sync(0xffffffffu, s, o));

#pragma unroll
    for (int j = 0; j < 5; j++) {
        int c = lane + j * 32;
        if (c < NCLS) {
            g_probs[(size_t)warp * NCLS + c] = __fdiv_rn(v[j], s);
            out[(size_t)warp * NCLS + c]     = row[c];   // obj_dists2 = logits verbatim
        }
    }
}

// ---------------- 2) W transpose + zero-pad --------------------------------
__global__ void wprep_kernel(const float* __restrict__ W) {
    int idx = blockIdx.x * 256 + threadIdx.x;
    if (idx >= RELN * RELK) return;
    int c = idx >> 12;          // 0..50
    int k = idx & 4095;
    g_Wt[(size_t)k * RELNP + c] = W[idx];
}

// ---------------- 3) per-class stable descending sort (bitonic, 1024) ------
// key = (score_bits << 32) | (1023 - idx): descending score, ascending idx on ties
__global__ void sort_kernel(const float* __restrict__ boxes) {
    __shared__ unsigned long long key[NBX];
    int c = blockIdx.x;
    int t = threadIdx.x;         // 0..511

#pragma unroll
    for (int e = 0; e < 2; e++) {
        int i = t + e * 512;
        unsigned sb = __float_as_uint(g_probs[(size_t)i * NCLS + c + 1]);  // probs >= 0
        key[i] = ((unsigned long long)sb << 32) | (unsigned)(1023 - i);
    }
    __syncthreads();

    for (int k = 2; k <= 1024; k <<= 1) {
        for (int j = k >> 1; j > 0; j >>= 1) {
#pragma unroll
            for (int e = 0; e < 2; e++) {
                int tid = t + e * 512;
                int ixj = tid ^ j;
                if (ixj > tid) {
                    bool desc = ((tid & k) == 0);
                    unsigned long long a = key[tid], b = key[ixj];
                    bool sw = desc ? (a < b) : (a > b);
                    if (sw) { key[tid] = b; key[ixj] = a; }
                }
            }
            __syncthreads();
        }
    }

#pragma unroll
    for (int e = 0; e < 2; e++) {
        int i   = t + e * 512;
        int idx = 1023 - (int)(key[i] & 1023u);
        g_order[c * NBX + i] = idx;
        const float4 bx = *reinterpret_cast<const float4*>(
            boxes + ((size_t)idx * NCLS + c + 1) * 4);
        g_sbox[c * NBX + i]  = bx;
        g_sarea[c * NBX + i] = __fmul_rn(__fsub_rn(bx.z, bx.x), __fsub_rn(bx.w, bx.y));
    }
}

// ---------------- 4) pairwise suppression mask (triangular blocks) ---------
__global__ void mask_kernel() {
    int cb = blockIdx.x, rb = blockIdx.y, c = blockIdx.z;
    int t  = threadIdx.x;                       // 0..63
    int i  = rb * 64 + t;
    unsigned long long* mp = g_mask + ((size_t)c * 16 + cb) * NBX + i;

    if (cb < rb) { *mp = 0ULL; return; }

    __shared__ float4 cbox[64];
    __shared__ float  carea[64];
    cbox[t]  = g_sbox[c * NBX + cb * 64 + t];
    carea[t] = g_sarea[c * NBX + cb * 64 + t];
    __syncthreads();

    float4 rbx = g_sbox[c * NBX + i];
    float  ra  = g_sarea[c * NBX + i];

    unsigned long long bits = 0ULL;
#pragma unroll 4
    for (int j = 0; j < 64; j++) {
        float4 cj = cbox[j];
        float ix1 = fmaxf(rbx.x, cj.x);
        float iy1 = fmaxf(rbx.y, cj.y);
        float ix2 = fminf(rbx.z, cj.z);
        float iy2 = fminf(rbx.w, cj.w);
        float iw  = fmaxf(__fsub_rn(ix2, ix1), 0.f);
        float ih  = fmaxf(__fsub_rn(iy2, iy1), 0.f);
        float inter = __fmul_rn(iw, ih);
        float denom = __fadd_rn(__fsub_rn(__fadd_rn(ra, carea[j]), inter), 1e-10f);
        float hi = __fmul_rn(denom, 0.30005f);
        float lo = __fmul_rn(denom, 0.29995f);
        bool sup;
        if (inter >= hi)      sup = true;
        else if (inter <= lo) sup = false;
        else                  sup = (__fdiv_rn(inter, denom) > 0.3f);
        if (sup) bits |= (1ULL << j);
    }
    *mp = bits;
}

// ---------------- 5) greedy scan: 32-lane, u32 cols, prefetched ------------
// One warp per class. Lane l owns u32 column-group l (cols l*32..l*32+31),
// aliased onto the u64 mask (little-endian: low half = cols g*64..g*64+31).
// Per 32-row group g: loads for group g+1 prefetch behind the serial chain.
__global__ void scan_kernel() {
    int c    = blockIdx.x;
    int lane = threadIdx.x;   // 0..31
    const unsigned* mcol =
        reinterpret_cast<const unsigned*>(g_mask + ((size_t)c * 16 + (lane >> 1)) * NBX)
        + (lane & 1);         // row r lives at mcol[2*r]
    const int* ord = g_order + c * NBX;
    unsigned char* kp = g_keep + c * NBX;

    unsigned v[32], w[32];
#pragma unroll
    for (int r = 0; r < 32; r++) v[r] = __ldg(mcol + 2 * r);

    unsigned remv = 0u;
    for (int g = 0; g < 32; g++) {
        if (g < 31) {
#pragma unroll
            for (int r = 0; r < 32; r++) w[r] = __ldg(mcol + 2 * ((g + 1) * 32 + r));
        }
        unsigned kb = 0u;
        if (lane == g) {                       // in-group bits live in owner's column
            unsigned rg = remv;
#pragma unroll
            for (int r = 0; r < 32; r++) {
                if (((rg >> r) & 1u) == 0u) {
                    kb |= 1u << r;
                    rg |= v[r];                // over-OR of decided bits is harmless
                }
            }
            remv = rg;
        }
        kb = __shfl_sync(0xffffffffu, kb, g);

        unsigned acc = remv;
#pragma unroll
        for (int r = 0; r < 32; r++)
            if ((kb >> r) & 1u) acc |= v[r];
        remv = acc;

        if (lane == 0) {
#pragma unroll
            for (int r = 0; r < 32; r++)
                kp[ord[g * 32 + r]] = (unsigned char)((kb >> r) & 1u);
        }
#pragma unroll
        for (int r = 0; r < 32; r++) v[r] = w[r];
    }
}

// ---------------- 6) argmax over masked probs -> obj_preds -----------------
__global__ void argmax_kernel(float* __restrict__ out) {
    int n = blockIdx.x * 256 + threadIdx.x;
    if (n >= NBX) return;
    float best = -1.f;
    int   bc   = 0;
    for (int c = 0; c < NNMS; c++) {
        float v = g_keep[c * NBX + n] ? g_probs[(size_t)n * NCLS + c + 1] : 0.f;
        if (v > best) { best = v; bc = c; }
    }
    out[154624 + n] = (float)(bc + 1);
}

// ---------------- 7) GEMM partial: split-K x8, reg-prefetch pipeline -------
// block tile: 128 rows x 64 cols, 256 threads; thread: 8 rows x 4 cols (f32x2)
__global__ void __launch_bounds__(256) gemm_kernel(const float* __restrict__ A) {
    __shared__ __align__(16) float As[GK][132];   // [k][m], 528B row stride
    __shared__ __align__(16) float Bs[GK][64];    // [k][c]

    int tid = threadIdx.x;
    int rt  = blockIdx.x;       // 0..31 row tile
    int z   = blockIdx.y;       // 0..7  k-split
    int m0  = rt * 128;
    int k0  = z * KPER;
    int tc  = tid & 15;
    int tr  = tid >> 4;

    unsigned long long acc[4][4];
#pragma unroll
    for (int a = 0; a < 4; a++)
#pragma unroll
        for (int b = 0; b < 4; b++) acc[a][b] = 0ULL;

    const float* Ag = A + (size_t)m0 * RELK + k0;

    // per-thread staging coords
    int am[4], ak[4], bk[2], bc4[2];
#pragma unroll
    for (int it = 0; it < 4; it++) {
        int idx = tid + it * 256;
        am[it] = idx >> 3;
        ak[it] = (idx & 7) * 4;
    }
#pragma unroll
    for (int it = 0; it < 2; it++) {
        int f = tid + it * 256;
        bk[it]  = f >> 4;
        bc4[it] = (f & 15) * 4;
    }

    float4 pa[4], pb[2];
    // load chunk 0
#pragma unroll
    for (int it = 0; it < 4; it++)
        pa[it] = *reinterpret_cast<const float4*>(Ag + (size_t)am[it] * RELK + ak[it]);
#pragma unroll
    for (int it = 0; it < 2; it++)
        pb[it] = *reinterpret_cast<const float4*>(g_Wt + (size_t)(k0 + bk[it]) * RELNP + bc4[it]);
    // store chunk 0
#pragma unroll
    for (int it = 0; it < 4; it++) {
        As[ak[it] + 0][am[it]] = pa[it].x;
        As[ak[it] + 1][am[it]] = pa[it].y;
        As[ak[it] + 2][am[it]] = pa[it].z;
        As[ak[it] + 3][am[it]] = pa[it].w;
    }
#pragma unroll
    for (int it = 0; it < 2; it++)
        *reinterpret_cast<float4*>(&Bs[bk[it]][bc4[it]]) = pb[it];
    __syncthreads();

    for (int ch = 0; ch < NCH; ch++) {
        // prefetch next chunk into registers (LDG latency hidden by compute)
        if (ch + 1 < NCH) {
            int kc = (ch + 1) * GK;
#pragma unroll
            for (int it = 0; it < 4; it++)
                pa[it] = *reinterpret_cast<const float4*>(Ag + (size_t)am[it] * RELK + kc + ak[it]);
#pragma unroll
            for (int it = 0; it < 2; it++)
                pb[it] = *reinterpret_cast<const float4*>(
                    g_Wt + (size_t)(k0 + kc + bk[it]) * RELNP + bc4[it]);
        }
        // compute current chunk from smem
#pragma unroll
        for (int k = 0; k < GK; k++) {
            longlong2 aA = *reinterpret_cast<const longlong2*>(&As[k][tr * 8]);
            longlong2 aB = *reinterpret_cast<const longlong2*>(&As[k][tr * 8 + 4]);
            unsigned long long ar[4] = { (unsigned long long)aA.x, (unsigned long long)aA.y,
                                         (unsigned long long)aB.x, (unsigned long long)aB.y };
            float4 bv = *reinterpret_cast<const float4*>(&Bs[k][tc * 4]);
            unsigned long long bd[4] = { dup2(bv.x), dup2(bv.y), dup2(bv.z), dup2(bv.w) };
#pragma unroll
            for (int rp = 0; rp < 4; rp++)
#pragma unroll
                for (int cc = 0; cc < 4; cc++) ffma2(acc[rp][cc], ar[rp], bd[cc]);
        }
        __syncthreads();
        if (ch + 1 < NCH) {
#pragma unroll
            for (int it = 0; it < 4; it++) {
                As[ak[it] + 0][am[it]] = pa[it].x;
                As[ak[it] + 1][am[it]] = pa[it].y;
                As[ak[it] + 2][am[it]] = pa[it].z;
                As[ak[it] + 3][am[it]] = pa[it].w;
            }
#pragma unroll
            for (int it = 0; it < 2; it++)
                *reinterpret_cast<float4*>(&Bs[bk[it]][bc4[it]]) = pb[it];
            __syncthreads();
        }
    }

    float* P = g_psum + ((size_t)z * RELM + m0) * RELNP;
#pragma unroll
    for (int rp = 0; rp < 4; rp++) {
        int mr = tr * 8 + rp * 2;
#pragma unroll
        for (int cc = 0; cc < 4; cc++) {
            float lo, hi;
            unpack2(acc[rp][cc], lo, hi);
            P[(size_t)(mr + 0) * RELNP + tc * 4 + cc] = lo;
            P[(size_t)(mr + 1) * RELNP + tc * 4 + cc] = hi;
        }
    }
}

// ---------------- 8) split-K reduce + bias -> rel_dists --------------------
__global__ void reduce_kernel(const float* __restrict__ b, float* __restrict__ out) {
    int idx = blockIdx.x * 256 + threadIdx.x;
    if (idx >= RELM * RELN) return;
    int m = idx / RELN;
    int c = idx - m * RELN;
    float s = b[c];
#pragma unroll
    for (int z = 0; z < KSPL; z++) s += g_psum[((size_t)z * RELM + m) * RELNP + c];
    out[154624 + 1024 + idx] = s;
}

// ---------------- launch ----------------------------------------------------
extern "C" void kernel_launch(void* const* d_in, const int* in_sizes, int n_in,
                              void* d_out, int out_size) {
    const float *logits = nullptr, *vr = nullptr, *boxes = nullptr, *W = nullptr, *bb = nullptr;
    for (int i = 0; i < n_in; i++) {
        switch (in_sizes[i]) {
            case 154624:   logits = (const float*)d_in[i]; break;
            case 16777216: vr     = (const float*)d_in[i]; break;
            case 618496:   boxes  = (const float*)d_in[i]; break;
            case 208896:   W      = (const float*)d_in[i]; break;
            case 51:       bb     = (const float*)d_in[i]; break;
        }
    }
    float* out = (float*)d_out;

    softmax_kernel<<<128, 256>>>(logits, out);
    wprep_kernel<<<(RELN * RELK + 255) / 256, 256>>>(W);
    sort_kernel<<<NNMS, 512>>>(boxes);
    mask_kernel<<<dim3(16, 16, NNMS), 64>>>();
    scan_kernel<<<NNMS, 32>>>();
    argmax_kernel<<<4, 256>>>(out);
    gemm_kernel<<<dim3(32, KSPL), 256>>>(vr);
    reduce_kernel<<<(RELM * RELN + 255) / 256, 256>>>(bb, out);
}

// round 6
// speedup vs baseline: 1.1730x; 1.0906x over previous
#include <cuda_runtime.h>
#include <cuda_bf16.h>
#include <cstdint>
#include <cstddef>

#define NBX  1024      // boxes
#define NCLS 151       // classes incl background
#define NNMS 150       // nms classes
#define RELK 4096
#define RELM 4096
#define RELN 51
#define RELNP 64       // padded cols
#define GK   32        // gemm k-chunk
#define KSPL 8         // split-K factor
#define KPER (RELK / KSPL)        // 512 k per split
#define NCH  (KPER / GK)          // 16 chunks per split

// IoU band thresholds: lambda = 0.3/1.3; certain-suppress if inter > LHI*s,
// certain-keep if inter < LLO*s, else exact-reference fallback. s = area_i+area_j.
#define L_HI 0.2308385f
#define L_LO 0.2306999f

// ---------------- persistent device scratch (no allocation allowed) --------
static __device__ float                g_probs[NBX * NCLS];
static __device__ int                  g_order[NNMS * NBX];
static __device__ __align__(16) float4 g_sbox[NNMS * NBX];
static __device__ float                g_sarea[NNMS * NBX];
// mask layout: [class][colgroup64(16)][row i (1024)]  (coalesced writes)
static __device__ unsigned long long   g_mask[(size_t)NNMS * 16 * NBX];
static __device__ unsigned char        g_keep[NNMS * NBX];
static __device__ __align__(16) float  g_Wt[RELK * RELNP];   // W^T zero-padded
static __device__ float                g_psum[KSPL * (size_t)RELM * RELNP];

// ---------------- f32x2 packed-math helpers --------------------------------
__device__ __forceinline__ unsigned long long dup2(float x) {
    unsigned long long r;
    asm("mov.b64 %0, {%1, %1};" : "=l"(r) : "f"(x));
    return r;
}
__device__ __forceinline__ void ffma2(unsigned long long& d,
                                      unsigned long long a,
                                      unsigned long long b) {
    asm("fma.rn.f32x2 %0, %1, %2, %0;" : "+l"(d) : "l"(a), "l"(b));
}
__device__ __forceinline__ void unpack2(unsigned long long v, float& lo, float& hi) {
    unsigned a, b;
    asm("mov.b64 {%0, %1}, %2;" : "=r"(a), "=r"(b) : "l"(v));
    lo = __uint_as_float(a);
    hi = __uint_as_float(b);
}

// ---------------- 1) softmax per box + copy logits to out ------------------
__global__ void softmax_kernel(const float* __restrict__ logits, float* __restrict__ out) {
    int warp = (blockIdx.x * blockDim.x + threadIdx.x) >> 5;
    int lane = threadIdx.x & 31;
    if (warp >= NBX) return;
    const float* row = logits + (size_t)warp * NCLS;

    float v[5];
    float mx = -3.402823466e38f;
#pragma unroll
    for (int j = 0; j < 5; j++) {
        int c = lane + j * 32;
        v[j]  = (c < NCLS) ? row[c] : -3.402823466e38f;
        mx    = fmaxf(mx, v[j]);
    }
#pragma unroll
    for (int o = 16; o; o >>= 1) mx = fmaxf(mx, __shfl_xor_sync(0xffffffffu, mx, o));

    float s = 0.f;
#pragma unroll
    for (int j = 0; j < 5; j++) {
        int c = lane + j * 32;
        if (c < NCLS) {
            v[j] = expf(__fsub_rn(v[j], mx));
            s    = __fadd_rn(s, v[j]);
        }
    }
#pragma unroll
    for (int o = 16; o; o >>= 1) s = __fadd_rn(s, __shfl_xor_sync(0xffffffffu, s, o));

#pragma unroll
    for (int j = 0; j < 5; j++) {
        int c = lane + j * 32;
        if (c < NCLS) {
            g_probs[(size_t)warp * NCLS + c] = __fdiv_rn(v[j], s);
            out[(size_t)warp * NCLS + c]     = row[c];   // obj_dists2 = logits verbatim
        }
    }
}

// ---------------- 2) W transpose + zero-pad --------------------------------
__global__ void wprep_kernel(const float* __restrict__ W) {
    int idx = blockIdx.x * 256 + threadIdx.x;
    if (idx >= RELN * RELK) return;
    int c = idx >> 12;          // 0..50
    int k = idx & 4095;
    g_Wt[(size_t)k * RELNP + c] = W[idx];
}

// ---------------- 3) per-class stable descending sort (bitonic, 1024) ------
__global__ void sort_kernel(const float* __restrict__ boxes) {
    __shared__ unsigned long long key[NBX];
    int c = blockIdx.x;
    int t = threadIdx.x;         // 0..511

#pragma unroll
    for (int e = 0; e < 2; e++) {
        int i = t + e * 512;
        unsigned sb = __float_as_uint(g_probs[(size_t)i * NCLS + c + 1]);  // probs >= 0
        key[i] = ((unsigned long long)sb << 32) | (unsigned)(1023 - i);
    }
    __syncthreads();

    for (int k = 2; k <= 1024; k <<= 1) {
        for (int j = k >> 1; j > 0; j >>= 1) {
#pragma unroll
            for (int e = 0; e < 2; e++) {
                int tid = t + e * 512;
                int ixj = tid ^ j;
                if (ixj > tid) {
                    bool desc = ((tid & k) == 0);
                    unsigned long long a = key[tid], b = key[ixj];
                    bool sw = desc ? (a < b) : (a > b);
                    if (sw) { key[tid] = b; key[ixj] = a; }
                }
            }
            __syncthreads();
        }
    }

#pragma unroll
    for (int e = 0; e < 2; e++) {
        int i   = t + e * 512;
        int idx = 1023 - (int)(key[i] & 1023u);
        g_order[c * NBX + i] = idx;
        const float4 bx = *reinterpret_cast<const float4*>(
            boxes + ((size_t)idx * NCLS + c + 1) * 4);
        g_sbox[c * NBX + i]  = bx;
        g_sarea[c * NBX + i] = __fmul_rn(__fsub_rn(bx.z, bx.x), __fsub_rn(bx.w, bx.y));
    }
}

// ---------------- 4) pairwise suppression mask: branchless band ------------
// grid (cb=16, rb=16, class=150), 64 threads; thread = row box, 64 cols unrolled.
__global__ void mask_kernel() {
    int cb = blockIdx.x, rb = blockIdx.y, c = blockIdx.z;
    int t  = threadIdx.x;                       // 0..63
    int i  = rb * 64 + t;
    unsigned long long* mp = g_mask + ((size_t)c * 16 + cb) * NBX + i;

    if (cb < rb) { *mp = 0ULL; return; }

    __shared__ float4 cbox[64];
    __shared__ float  carea[64];
    cbox[t]  = g_sbox[c * NBX + cb * 64 + t];
    carea[t] = g_sarea[c * NBX + cb * 64 + t];
    __syncthreads();

    const float4 rbx = g_sbox[c * NBX + i];
    const float  ra  = g_sarea[c * NBX + i];

    unsigned m0 = 0u, m1 = 0u, amb = 0u;
#pragma unroll
    for (int j = 0; j < 64; j++) {
        float4 cj = cbox[j];
        float ix1 = fmaxf(rbx.x, cj.x);
        float iy1 = fmaxf(rbx.y, cj.y);
        float ix2 = fminf(rbx.z, cj.z);
        float iy2 = fminf(rbx.w, cj.w);
        float iw  = fmaxf(__fsub_rn(ix2, ix1), 0.f);
        float ih  = fmaxf(__fsub_rn(iy2, iy1), 0.f);
        float inter = __fmul_rn(iw, ih);
        float s   = __fadd_rn(ra, carea[j]);
        float rhi = __fmaf_rn(L_HI, s, -inter);   // <0  => certainly suppressed
        float rlo = __fmaf_rn(L_LO, s, -inter);   // >=0 => certainly kept
        unsigned hb = __float_as_uint(rhi);
        unsigned lb = __float_as_uint(rlo);
        unsigned sb = hb >> 31;                   // 1 if certain-suppress
        if (j < 32) m0 += sb << j;                // IMAD, branch-free (const shift)
        else        m1 += sb << (j - 32);
        amb |= (~hb) & lb;                        // sign bit: in-band => ambiguous
    }

    if (amb >> 31) {   // rare (~1e-5/pair): redo row exactly as the reference
        m0 = 0u; m1 = 0u;
        for (int j = 0; j < 64; j++) {
            float4 cj = cbox[j];
            float ix1 = fmaxf(rbx.x, cj.x);
            float iy1 = fmaxf(rbx.y, cj.y);
            float ix2 = fminf(rbx.z, cj.z);
            float iy2 = fminf(rbx.w, cj.w);
            float iw  = fmaxf(__fsub_rn(ix2, ix1), 0.f);
            float ih  = fmaxf(__fsub_rn(iy2, iy1), 0.f);
            float inter = __fmul_rn(iw, ih);
            float denom = __fadd_rn(__fsub_rn(__fadd_rn(ra, carea[j]), inter), 1e-10f);
            unsigned sup = (__fdiv_rn(inter, denom) > 0.3f) ? 1u : 0u;
            if (j < 32) m0 |= sup << j;
            else        m1 |= sup << (j - 32);
        }
    }

    *mp = ((unsigned long long)m1 << 32) | m0;   // coalesced u64 store
}

// ---------------- 5) greedy scan: 32-lane, u32 cols, prefetched ------------
__global__ void scan_kernel() {
    int c    = blockIdx.x;
    int lane = threadIdx.x;   // 0..31
    const unsigned* mcol =
        reinterpret_cast<const unsigned*>(g_mask + ((size_t)c * 16 + (lane >> 1)) * NBX)
        + (lane & 1);         // row r lives at mcol[2*r]
    const int* ord = g_order + c * NBX;
    unsigned char* kp = g_keep + c * NBX;

    unsigned v[32], w[32];
#pragma unroll
    for (int r = 0; r < 32; r++) v[r] = __ldg(mcol + 2 * r);

    unsigned remv = 0u;
    for (int g = 0; g < 32; g++) {
        if (g < 31) {
#pragma unroll
            for (int r = 0; r < 32; r++) w[r] = __ldg(mcol + 2 * ((g + 1) * 32 + r));
        }
        unsigned kb = 0u;
        if (lane == g) {
            unsigned rg = remv;
#pragma unroll
            for (int r = 0; r < 32; r++) {
                if (((rg >> r) & 1u) == 0u) {
                    kb |= 1u << r;
                    rg |= v[r];
                }
            }
            remv = rg;
        }
        kb = __shfl_sync(0xffffffffu, kb, g);

        unsigned acc = remv;
#pragma unroll
        for (int r = 0; r < 32; r++)
            if ((kb >> r) & 1u) acc |= v[r];
        remv = acc;

        if (lane == 0) {
#pragma unroll
            for (int r = 0; r < 32; r++)
                kp[ord[g * 32 + r]] = (unsigned char)((kb >> r) & 1u);
        }
#pragma unroll
        for (int r = 0; r < 32; r++) v[r] = w[r];
    }
}

// ---------------- 6) argmax over masked probs -> obj_preds -----------------
__global__ void argmax_kernel(float* __restrict__ out) {
    int n = blockIdx.x * 256 + threadIdx.x;
    if (n >= NBX) return;
    float best = -1.f;
    int   bc   = 0;
    for (int c = 0; c < NNMS; c++) {
        float v = g_keep[c * NBX + n] ? g_probs[(size_t)n * NCLS + c + 1] : 0.f;
        if (v > best) { best = v; bc = c; }
    }
    out[154624 + n] = (float)(bc + 1);
}

// ---------------- 7) GEMM partial: split-K x8, reg-prefetch pipeline -------
__global__ void __launch_bounds__(256) gemm_kernel(const float* __restrict__ A) {
    __shared__ __align__(16) float As[GK][132];
    __shared__ __align__(16) float Bs[GK][64];

    int tid = threadIdx.x;
    int rt  = blockIdx.x;
    int z   = blockIdx.y;
    int m0  = rt * 128;
    int k0  = z * KPER;
    int tc  = tid & 15;
    int tr  = tid >> 4;

    unsigned long long acc[4][4];
#pragma unroll
    for (int a = 0; a < 4; a++)
#pragma unroll
        for (int b = 0; b < 4; b++) acc[a][b] = 0ULL;

    const float* Ag = A + (size_t)m0 * RELK + k0;

    int am[4], ak[4], bk[2], bc4[2];
#pragma unroll
    for (int it = 0; it < 4; it++) {
        int idx = tid + it * 256;
        am[it] = idx >> 3;
        ak[it] = (idx & 7) * 4;
    }
#pragma unroll
    for (int it = 0; it < 2; it++) {
        int f = tid + it * 256;
        bk[it]  = f >> 4;
        bc4[it] = (f & 15) * 4;
    }

    float4 pa[4], pb[2];
#pragma unroll
    for (int it = 0; it < 4; it++)
        pa[it] = *reinterpret_cast<const float4*>(Ag + (size_t)am[it] * RELK + ak[it]);
#pragma unroll
    for (int it = 0; it < 2; it++)
        pb[it] = *reinterpret_cast<const float4*>(g_Wt + (size_t)(k0 + bk[it]) * RELNP + bc4[it]);
#pragma unroll
    for (int it = 0; it < 4; it++) {
        As[ak[it] + 0][am[it]] = pa[it].x;
        As[ak[it] + 1][am[it]] = pa[it].y;
        As[ak[it] + 2][am[it]] = pa[it].z;
        As[ak[it] + 3][am[it]] = pa[it].w;
    }
#pragma unroll
    for (int it = 0; it < 2; it++)
        *reinterpret_cast<float4*>(&Bs[bk[it]][bc4[it]]) = pb[it];
    __syncthreads();

    for (int ch = 0; ch < NCH; ch++) {
        if (ch + 1 < NCH) {
            int kc = (ch + 1) * GK;
#pragma unroll
            for (int it = 0; it < 4; it++)
                pa[it] = *reinterpret_cast<const float4*>(Ag + (size_t)am[it] * RELK + kc + ak[it]);
#pragma unroll
            for (int it = 0; it < 2; it++)
                pb[it] = *reinterpret_cast<const float4*>(
                    g_Wt + (size_t)(k0 + kc + bk[it]) * RELNP + bc4[it]);
        }
#pragma unroll
        for (int k = 0; k < GK; k++) {
            longlong2 aA = *reinterpret_cast<const longlong2*>(&As[k][tr * 8]);
            longlong2 aB = *reinterpret_cast<const longlong2*>(&As[k][tr * 8 + 4]);
            unsigned long long ar[4] = { (unsigned long long)aA.x, (unsigned long long)aA.y,
                                         (unsigned long long)aB.x, (unsigned long long)aB.y };
            float4 bv = *reinterpret_cast<const float4*>(&Bs[k][tc * 4]);
            unsigned long long bd[4] = { dup2(bv.x), dup2(bv.y), dup2(bv.z), dup2(bv.w) };
#pragma unroll
            for (int rp = 0; rp < 4; rp++)
#pragma unroll
                for (int cc = 0; cc < 4; cc++) ffma2(acc[rp][cc], ar[rp], bd[cc]);
        }
        __syncthreads();
        if (ch + 1 < NCH) {
#pragma unroll
            for (int it = 0; it < 4; it++) {
                As[ak[it] + 0][am[it]] = pa[it].x;
                As[ak[it] + 1][am[it]] = pa[it].y;
                As[ak[it] + 2][am[it]] = pa[it].z;
                As[ak[it] + 3][am[it]] = pa[it].w;
            }
#pragma unroll
            for (int it = 0; it < 2; it++)
                *reinterpret_cast<float4*>(&Bs[bk[it]][bc4[it]]) = pb[it];
            __syncthreads();
        }
    }

    float* P = g_psum + ((size_t)z * RELM + m0) * RELNP;
#pragma unroll
    for (int rp = 0; rp < 4; rp++) {
        int mr = tr * 8 + rp * 2;
#pragma unroll
        for (int cc = 0; cc < 4; cc++) {
            float lo, hi;
            unpack2(acc[rp][cc], lo, hi);
            P[(size_t)(mr + 0) * RELNP + tc * 4 + cc] = lo;
            P[(size_t)(mr + 1) * RELNP + tc * 4 + cc] = hi;
        }
    }
}

// ---------------- 8) split-K reduce + bias -> rel_dists --------------------
__global__ void reduce_kernel(const float* __restrict__ b, float* __restrict__ out) {
    int idx = blockIdx.x * 256 + threadIdx.x;
    if (idx >= RELM * RELN) return;
    int m = idx / RELN;
    int c = idx - m * RELN;
    float s = b[c];
#pragma unroll
    for (int z = 0; z < KSPL; z++) s += g_psum[((size_t)z * RELM + m) * RELNP + c];
    out[154624 + 1024 + idx] = s;
}

// ---------------- launch ----------------------------------------------------
extern "C" void kernel_launch(void* const* d_in, const int* in_sizes, int n_in,
                              void* d_out, int out_size) {
    const float *logits = nullptr, *vr = nullptr, *boxes = nullptr, *W = nullptr, *bb = nullptr;
    for (int i = 0; i < n_in; i++) {
        switch (in_sizes[i]) {
            case 154624:   logits = (const float*)d_in[i]; break;
            case 16777216: vr     = (const float*)d_in[i]; break;
            case 618496:   boxes  = (const float*)d_in[i]; break;
            case 208896:   W      = (const float*)d_in[i]; break;
            case 51:       bb     = (const float*)d_in[i]; break;
        }
    }
    float* out = (float*)d_out;

    softmax_kernel<<<128, 256>>>(logits, out);
    wprep_kernel<<<(RELN * RELK + 255) / 256, 256>>>(W);
    sort_kernel<<<NNMS, 512>>>(boxes);
    mask_kernel<<<dim3(16, 16, NNMS), 64>>>();
    scan_kernel<<<NNMS, 32>>>();
    argmax_kernel<<<4, 256>>>(out);
    gemm_kernel<<<dim3(32, KSPL), 256>>>(vr);
    reduce_kernel<<<(RELM * RELN + 255) / 256, 256>>>(bb, out);
}